// round 7
// baseline (speedup 1.0000x reference)
#include <cuda_runtime.h>
#include <cstdint>

#define N 8192
#define D 128
#define G 8                   // column stripes
#define MT 64                 // rows per CTA
#define NTILE 128             // cols per tile
#define NTILES 8              // tiles per CTA
#define KEEP 6                // candidates kept per (row, stripe)
#define STRB 144              // smem tile row stride in bytes (144 == 16 mod 128)
#define TBYTES 18432          // 128*144

// dynamic smem layout (bytes)
#define SM_SQ    0            // 2 * 128 ints = 1024
#define SM_A     1024         // 64*144 = 9216
#define SM_B     10240        // 2 * 18432 = 36864
#define SM_SCR   1024         // scratch over A after tile loop: 64*KEEP uints
#define SM_TOTAL 47104

__device__ uint32_t g_xq[N * 32];     // packed int8 rows (128 B each)
__device__ int      g_sq9[N];         // (sum of q^2) << 9
__device__ int      g_topI[N * G * KEEP];
__device__ float    g_hinge[N];

__device__ __forceinline__ bool better(float d1, int i1, float d2, int i2) {
    return (d1 < d2) || (d1 == d2 && i1 < i2);
}
__device__ __forceinline__ uint32_t smem_u32(const void* p) {
    uint32_t a;
    asm("{ .reg .u64 t; cvta.to.shared.u64 t, %1; cvt.u32.u64 %0, t; }" : "=r"(a) : "l"(p));
    return a;
}
__device__ __forceinline__ void ldsm_x4(uint32_t* r, uint32_t addr) {
    asm volatile("ldmatrix.sync.aligned.m8n8.x4.shared.b16 {%0,%1,%2,%3}, [%4];"
                 : "=r"(r[0]), "=r"(r[1]), "=r"(r[2]), "=r"(r[3]) : "r"(addr));
}
__device__ __forceinline__ void imma16832(int* d, const uint32_t* a, uint32_t b0, uint32_t b1) {
    asm volatile("mma.sync.aligned.m16n8k32.row.col.s32.s8.s8.s32 "
                 "{%0,%1,%2,%3}, {%4,%5,%6,%7}, {%8,%9}, {%0,%1,%2,%3};"
                 : "+r"(d[0]), "+r"(d[1]), "+r"(d[2]), "+r"(d[3])
                 : "r"(a[0]), "r"(a[1]), "r"(a[2]), "r"(a[3]), "r"(b0), "r"(b1));
}
__device__ __forceinline__ void cp_async16(uint32_t dst, const void* src) {
    asm volatile("cp.async.cg.shared.global [%0], [%1], 16;" :: "r"(dst), "l"(src));
}
__device__ __forceinline__ void cp_commit() { asm volatile("cp.async.commit_group;" ::: "memory"); }
__device__ __forceinline__ void cp_wait1() { asm volatile("cp.async.wait_group 1;" ::: "memory"); }
__device__ __forceinline__ void cp_wait0() { asm volatile("cp.async.wait_group 0;" ::: "memory"); }

// branchless depth-4 sorted insert on uint keys (8 IMNMX)
__device__ __forceinline__ void ins4(uint32_t c, uint32_t* t) {
#pragma unroll
    for (int s = 0; s < 4; s++) {
        uint32_t lo = min(t[s], c);
        c = max(t[s], c);
        t[s] = lo;
    }
}
// branchless insert into sorted-KEEP list
__device__ __forceinline__ void ins6(uint32_t c, uint32_t* t) {
#pragma unroll
    for (int s = 0; s < KEEP; s++) {
        uint32_t lo = min(t[s], c);
        c = max(t[s], c);
        t[s] = lo;
    }
}

// ---------------------------------------------------------------------------
// Kernel P: quantize to int8 (scale 1/24), pack, integer row norms << 9
// ---------------------------------------------------------------------------
__global__ void prep_kernel(const float* __restrict__ x) {
    int row  = blockIdx.x * 8 + (threadIdx.x >> 5);
    int lane = threadIdx.x & 31;
    float4 v = ((const float4*)(x + row * D))[lane];
    int q0 = min(max(__float2int_rn(v.x * 24.f), -127), 127);
    int q1 = min(max(__float2int_rn(v.y * 24.f), -127), 127);
    int q2 = min(max(__float2int_rn(v.z * 24.f), -127), 127);
    int q3 = min(max(__float2int_rn(v.w * 24.f), -127), 127);
    g_xq[row * 32 + lane] = (uint32_t)(q0 & 255) | ((uint32_t)(q1 & 255) << 8) |
                            ((uint32_t)(q2 & 255) << 16) | ((uint32_t)(q3 & 255) << 24);
    int s = q0 * q0 + q1 * q1 + q2 * q2 + q3 * q3;
#pragma unroll
    for (int o = 16; o; o >>= 1) s += __shfl_xor_sync(0xffffffffu, s, o);
    if (lane == 0) g_sq9[row] = s << 9;
}

// ---------------------------------------------------------------------------
// Kernel B: int8 Gram + branchless integer-key selection.
// Grid (G, 128), 256 threads = 8 warps: wr = w>>1 (16-row group), wc = w&1
// (64-col group). Key = (d2i << 9) | (u<<6 | col-within-64).
// ---------------------------------------------------------------------------
__global__ __launch_bounds__(256, 2) void gram_top_kernel() {
    extern __shared__ char sm[];
    int* sqc9 = (int*)(sm + SM_SQ);
    const uint32_t smBase = smem_u32(sm);
    const uint32_t smA = smBase + SM_A;
    const uint32_t smB = smBase + SM_B;

    const int tid = threadIdx.x;
    const int w = tid >> 5, l = tid & 31;
    const int wr = w >> 1, wc = w & 1;
    const int lane2 = l & 3;
    const int bx = blockIdx.x;
    const int rowBase = blockIdx.y * MT;

    // resident A tile: 64 rows x 128 B, stride 144
    {
#pragma unroll
        for (int v = 0; v < 2; v++) {
            int i = tid + v * 256;           // 512 uint4 chunks
            int r = i >> 3, c16 = i & 7;
            uint4 val = ((const uint4*)g_xq)[(rowBase + r) * 8 + c16];
            *(uint4*)(sm + SM_A + r * STRB + c16 * 16) = val;
        }
    }

    // prologue: B(0) + sq(0)
    {
#pragma unroll
        for (int v = 0; v < 4; v++) {
            int i = tid + v * 256;           // 1024 16B chunks
            int col = i >> 3, c16 = i & 7;
            cp_async16(smB + (uint32_t)(col * STRB + c16 * 16),
                       (const char*)g_xq + (bx * NTILE + col) * 128 + c16 * 16);
        }
        cp_commit();
        if (tid < 128) sqc9[tid] = g_sq9[bx * NTILE + tid];
    }

    uint32_t sqR9[2];
    sqR9[0] = (uint32_t)g_sq9[rowBase + wr * 16 + (l >> 2)];
    sqR9[1] = (uint32_t)g_sq9[rowBase + wr * 16 + (l >> 2) + 8];

    uint32_t kd[2][4];
#pragma unroll
    for (int h = 0; h < 2; h++)
#pragma unroll
        for (int s = 0; s < 4; s++) kd[h][s] = 0xFFFFFFFFu;

    const uint32_t aBase = smA + (uint32_t)((wr * 16 + (l & 15)) * STRB) + ((l >> 4) & 1) * 16;
    const uint32_t bOff  = (uint32_t)((wc * 64 + (l & 7) + ((l >> 4) & 1) * 8) * STRB) + ((l >> 3) & 1) * 16;

    int rsq = 0;
    for (int u = 0; u < NTILES; u++) {
        if (u < NTILES - 1) {
            const int cb1 = (bx + (u + 1) * G) * NTILE;
            const uint32_t dstB = smB + (uint32_t)(((u + 1) & 1) * TBYTES);
#pragma unroll
            for (int v = 0; v < 4; v++) {
                int i = tid + v * 256;
                int col = i >> 3, c16 = i & 7;
                cp_async16(dstB + (uint32_t)(col * STRB + c16 * 16),
                           (const char*)g_xq + (cb1 + col) * 128 + c16 * 16);
            }
            cp_commit();
            if (tid < 128) rsq = g_sq9[cb1 + tid];   // LDG hidden by MMA below
            cp_wait1();
        } else {
            cp_wait0();
        }
        __syncthreads();

        int acc[8][4];
#pragma unroll
        for (int nf = 0; nf < 8; nf++)
#pragma unroll
            for (int q = 0; q < 4; q++) acc[nf][q] = 0;

        const uint32_t bBase = smB + (uint32_t)((u & 1) * TBYTES) + bOff;
#pragma unroll
        for (int ks = 0; ks < 4; ks++) {            // 4 chunks of k32
            uint32_t a[4], b[4][4];
            ldsm_x4(a, aBase + ks * 32);
#pragma unroll
            for (int nf4 = 0; nf4 < 4; nf4++)
                ldsm_x4(b[nf4], bBase + nf4 * 16 * STRB + ks * 32);
#pragma unroll
            for (int nf = 0; nf < 8; nf++)
                imma16832(acc[nf], a, b[nf >> 1][(nf & 1) * 2], b[nf >> 1][(nf & 1) * 2 + 1]);
        }

        // branchless integer-key epilogue
        const int* sq = sqc9 + (u & 1) * 128;
        const uint32_t idu = (uint32_t)(u << 6);
#pragma unroll
        for (int nf = 0; nf < 8; nf++)
#pragma unroll
            for (int q = 0; q < 2; q++) {
                int cloc = wc * 64 + nf * 8 + lane2 * 2 + q;
                uint32_t base = (uint32_t)sq[cloc] + idu +
                                (uint32_t)((nf << 3) | (lane2 << 1) | q);
#pragma unroll
                for (int h = 0; h < 2; h++) {
                    uint32_t key = sqR9[h] + base + (uint32_t)(acc[nf][h * 2 + q] * -1024);
                    ins4(key, kd[h]);
                }
            }

        if (u < NTILES - 1 && tid < 128) sqc9[((u + 1) & 1) * 128 + tid] = rsq;
        __syncthreads();
    }

    // merge across the 4 lanes of each quad
    uint32_t t6[2][KEEP];
#pragma unroll
    for (int h = 0; h < 2; h++) {
#pragma unroll
        for (int s = 0; s < 4; s++) t6[h][s] = kd[h][s];
#pragma unroll
        for (int s = 4; s < KEEP; s++) t6[h][s] = 0xFFFFFFFFu;
#pragma unroll
        for (int s = 0; s < 4; s++)
            ins6(__shfl_xor_sync(0xffffffffu, kd[h][s], 1), t6[h]);
        uint32_t o[KEEP];
#pragma unroll
        for (int s = 0; s < KEEP; s++) o[s] = __shfl_xor_sync(0xffffffffu, t6[h][s], 2);
#pragma unroll
        for (int s = 0; s < KEEP; s++) ins6(o[s], t6[h]);
    }

    // cross-wc merge: wc==1 publishes keys, wc==0 decodes + merges + writes
    uint32_t* scr = (uint32_t*)(sm + SM_SCR);
    __syncthreads();   // all ldsm reads of A done; scratch safe
    if (wc == 1 && lane2 == 0) {
#pragma unroll
        for (int h = 0; h < 2; h++) {
            int rl = wr * 16 + (l >> 2) + h * 8;
#pragma unroll
            for (int s = 0; s < KEEP; s++) scr[rl * KEEP + s] = t6[h][s];
        }
    }
    __syncthreads();
    if (wc == 0 && lane2 == 0) {
#pragma unroll
        for (int h = 0; h < 2; h++) {
            int rl = wr * 16 + (l >> 2) + h * 8;
            uint32_t rk[KEEP]; int rj[KEEP];
#pragma unroll
            for (int s = 0; s < KEEP; s++) {
                uint32_t id = t6[h][s] & 0x1FFu;
                rk[s] = t6[h][s];
                rj[s] = bx * NTILE + (int)(id >> 6) * (G * NTILE) + (int)(id & 63);
            }
#pragma unroll
            for (int e = 0; e < KEEP; e++) {
                uint32_t ck = scr[rl * KEEP + e];
                uint32_t id = ck & 0x1FFu;
                int cj = bx * NTILE + (int)(id >> 6) * (G * NTILE) + 64 + (int)(id & 63);
#pragma unroll
                for (int s = 0; s < KEEP; s++) {
                    bool lt = ck < rk[s];
                    uint32_t nk = lt ? ck : rk[s];
                    int      nj = lt ? cj : rj[s];
                    ck = lt ? rk[s] : ck;
                    cj = lt ? rj[s] : cj;
                    rk[s] = nk; rj[s] = nj;
                }
            }
            int row = rowBase + rl;
#pragma unroll
            for (int s = 0; s < KEEP; s++)
                g_topI[(row * G + bx) * KEEP + s] = rj[s];
        }
    }
}

// ---------------------------------------------------------------------------
// Kernel C: exact fp32 rescoring of 48 candidates -> true 5th NN -> hinge.
// ---------------------------------------------------------------------------
__global__ void finalize_kernel(const float* __restrict__ x, const float* __restrict__ p) {
    int row  = blockIdx.x * 8 + (threadIdx.x >> 5);
    int lane = threadIdx.x & 31;

    float4 xi = ((const float4*)(x + row * D))[lane];

    float t5d[5]; int t5i[5];
#pragma unroll
    for (int s = 0; s < 5; s++) { t5d[s] = __int_as_float(0x7f800000); t5i[s] = 0x7fffffff; }

    const int* cand = g_topI + row * G * KEEP;
    for (int c = 0; c < G * KEEP; c++) {
        int j = cand[c];
        float4 xj = ((const float4*)(x + j * D))[lane];
        float d0 = xi.x - xj.x, d1 = xi.y - xj.y, d2_ = xi.z - xj.z, d3 = xi.w - xj.w;
        float s = fmaf(d0, d0, fmaf(d1, d1, fmaf(d2_, d2_, d3 * d3)));
#pragma unroll
        for (int o = 16; o; o >>= 1) s += __shfl_xor_sync(0xffffffffu, s, o);
        float d2 = fmaxf(s, 1e-12f);
        if (better(d2, j, t5d[4], t5i[4])) {
            float cd = d2; int ci = j;
#pragma unroll
            for (int k = 0; k < 5; k++) {
                if (better(cd, ci, t5d[k], t5i[k])) {
                    float td = t5d[k]; t5d[k] = cd; cd = td;
                    int   ti = t5i[k]; t5i[k] = ci; ci = ti;
                }
            }
        }
    }
    int neg = t5i[4];

    float4 pi = ((const float4*)(p + row * D))[lane];
    float4 xn = ((const float4*)(x + neg * D))[lane];
    float ap0 = xi.x - pi.x + 1e-6f, ap1 = xi.y - pi.y + 1e-6f;
    float ap2 = xi.z - pi.z + 1e-6f, ap3 = xi.w - pi.w + 1e-6f;
    float an0 = xi.x - xn.x + 1e-6f, an1 = xi.y - xn.y + 1e-6f;
    float an2 = xi.z - xn.z + 1e-6f, an3 = xi.w - xn.w + 1e-6f;
    float sap = fmaf(ap0, ap0, fmaf(ap1, ap1, fmaf(ap2, ap2, ap3 * ap3)));
    float san = fmaf(an0, an0, fmaf(an1, an1, fmaf(an2, an2, an3 * an3)));
#pragma unroll
    for (int o = 16; o; o >>= 1) {
        sap += __shfl_xor_sync(0xffffffffu, sap, o);
        san += __shfl_xor_sync(0xffffffffu, san, o);
    }
    if (lane == 0)
        g_hinge[row] = fmaxf(sqrtf(sap) - sqrtf(san) + 0.3f, 0.f);
}

// ---------------------------------------------------------------------------
// Kernel D: deterministic fixed-schedule mean
// ---------------------------------------------------------------------------
__global__ void reduce_kernel(float* out) {
    __shared__ float sh[256];
    int tid = threadIdx.x;
    float s = 0.f;
    for (int i = tid; i < N; i += 256) s += g_hinge[i];
    sh[tid] = s;
    __syncthreads();
    for (int o = 128; o; o >>= 1) {
        if (tid < o) sh[tid] += sh[tid + o];
        __syncthreads();
    }
    if (tid == 0) out[0] = sh[0] * (1.0f / N);
}

// ---------------------------------------------------------------------------
extern "C" void kernel_launch(void* const* d_in, const int* in_sizes, int n_in,
                              void* d_out, int out_size) {
    const float* x   = (const float*)d_in[0];
    const float* pos = (const float*)d_in[1];
    float* out = (float*)d_out;

    cudaFuncSetAttribute(gram_top_kernel,
                         cudaFuncAttributeMaxDynamicSharedMemorySize, SM_TOTAL);

    prep_kernel<<<N / 8, 256>>>(x);
    gram_top_kernel<<<dim3(G, N / MT), 256, SM_TOTAL>>>();
    finalize_kernel<<<N / 8, 256>>>(x, pos);
    reduce_kernel<<<1, 256>>>(out);
}

// round 8
// speedup vs baseline: 1.5961x; 1.5961x over previous
#include <cuda_runtime.h>
#include <cuda_fp16.h>
#include <cstdint>

#define N 8192
#define D 128
#define G 8                   // column stripes
#define MT 64                 // rows per CTA
#define NTILE 128             // cols per tile
#define NTILES 8              // tiles per CTA
#define KEEP 5                // candidates kept per (row, stripe)
#define STRH 136              // smem tile row stride in halfs (272B)
#define TBYTES 34816          // 128*136*2

// dynamic smem layout (bytes)
#define SM_SQ    0            // 2 * 128 floats = 1024
#define SM_A     1024         // 64*272 = 17408
#define SM_B     18432        // 2 * 34816 = 69632
#define SM_SCR   1024         // scratch over A after frag preload: 64*KEEP uints
#define SM_TOTAL 88064

__device__ __half   g_xh[N * D];
__device__ float    g_sq[N];          // ||x_j||^2 + 512
__device__ int      g_topI[N * G * KEEP];
__device__ float    g_partial[1024];
__device__ unsigned g_cnt = 0;

__device__ __forceinline__ bool better(float d1, int i1, float d2, int i2) {
    return (d1 < d2) || (d1 == d2 && i1 < i2);
}
__device__ __forceinline__ uint32_t smem_u32(const void* p) {
    uint32_t a;
    asm("{ .reg .u64 t; cvta.to.shared.u64 t, %1; cvt.u32.u64 %0, t; }" : "=r"(a) : "l"(p));
    return a;
}
__device__ __forceinline__ void ldsm_x4(uint32_t* r, uint32_t addr) {
    asm volatile("ldmatrix.sync.aligned.m8n8.x4.shared.b16 {%0,%1,%2,%3}, [%4];"
                 : "=r"(r[0]), "=r"(r[1]), "=r"(r[2]), "=r"(r[3]) : "r"(addr));
}
__device__ __forceinline__ void mma16816(float* d, const uint32_t* a, uint32_t b0, uint32_t b1) {
    asm volatile("mma.sync.aligned.m16n8k16.row.col.f32.f16.f16.f32 "
                 "{%0,%1,%2,%3}, {%4,%5,%6,%7}, {%8,%9}, {%0,%1,%2,%3};"
                 : "+f"(d[0]), "+f"(d[1]), "+f"(d[2]), "+f"(d[3])
                 : "r"(a[0]), "r"(a[1]), "r"(a[2]), "r"(a[3]), "r"(b0), "r"(b1));
}
__device__ __forceinline__ void cp_async16(uint32_t dst, const void* src) {
    asm volatile("cp.async.cg.shared.global [%0], [%1], 16;" :: "r"(dst), "l"(src));
}
__device__ __forceinline__ void cp_commit() { asm volatile("cp.async.commit_group;" ::: "memory"); }
__device__ __forceinline__ void cp_wait1() { asm volatile("cp.async.wait_group 1;" ::: "memory"); }
__device__ __forceinline__ void cp_wait0() { asm volatile("cp.async.wait_group 0;" ::: "memory"); }

// branchless depth-4 sorted insert on uint keys
__device__ __forceinline__ void ins4(uint32_t c, uint32_t* t) {
#pragma unroll
    for (int s = 0; s < 4; s++) {
        uint32_t lo = min(t[s], c);
        c = max(t[s], c);
        t[s] = lo;
    }
}
// branchless insert into sorted-5 list
__device__ __forceinline__ void ins5(uint32_t c, uint32_t* t) {
#pragma unroll
    for (int s = 0; s < 5; s++) {
        uint32_t lo = min(t[s], c);
        c = max(t[s], c);
        t[s] = lo;
    }
}

// ---------------------------------------------------------------------------
// Kernel P: fp16 cast + (row norm + 512)
// ---------------------------------------------------------------------------
__global__ void prep_kernel(const float* __restrict__ x) {
    int row  = blockIdx.x * 8 + (threadIdx.x >> 5);
    int lane = threadIdx.x & 31;
    const float* xr = x + row * D;
    float s = 0.f;
#pragma unroll
    for (int kk = 0; kk < 4; kk++) {
        int k = lane + 32 * kk;
        float v = xr[k];
        g_xh[row * D + k] = __float2half_rn(v);
        s = fmaf(v, v, s);
    }
#pragma unroll
    for (int o = 16; o; o >>= 1) s += __shfl_xor_sync(0xffffffffu, s, o);
    if (lane == 0) g_sq[row] = s + 512.0f;
}

// ---------------------------------------------------------------------------
// Kernel B: approx fp16 Gram + branchless keyed selection.
// Grid (G, 128), 256 threads = 8 warps: wr = w>>1 (16-row group), wc = w&1
// (64-col group). Key = trunc_bits(sq_j + 512 - 2*dot) | id9 (row term dropped
// as rank-invariant). A fragments register-resident across the tile loop.
// ---------------------------------------------------------------------------
__global__ __launch_bounds__(256, 2) void gram_top_kernel() {
    extern __shared__ char sm[];
    float* sqc = (float*)(sm + SM_SQ);
    const uint32_t smBase = smem_u32(sm);
    const uint32_t smA = smBase + SM_A;
    const uint32_t smB = smBase + SM_B;

    const int tid = threadIdx.x;
    const int w = tid >> 5, l = tid & 31;
    const int wr = w >> 1, wc = w & 1;
    const int lane2 = l & 3;
    const int bx = blockIdx.x;
    const int rowBase = blockIdx.y * MT;

    // prologue: issue B(0) first (overlaps A smem fill)
    {
#pragma unroll
        for (int v = 0; v < 8; v++) {
            int i = tid + v * 256;
            int col = i >> 4, k8 = i & 15;
            cp_async16(smB + (uint32_t)(col * (STRH * 2) + k8 * 16),
                       g_xh + (bx * NTILE + col) * D + k8 * 8);
        }
        cp_commit();
        if (tid < 128) sqc[tid] = g_sq[bx * NTILE + tid];
    }

    // A tile to smem: 64 rows x 128 halfs, stride 136
    {
        const __half* Ag = g_xh + rowBase * D;
#pragma unroll
        for (int v = 0; v < 4; v++) {
            int i = tid + v * 256;
            int r = i >> 4, c8 = i & 15;
            uint4 val = *(const uint4*)(Ag + r * D + c8 * 8);
            *(uint4*)(sm + SM_A + r * (STRH * 2) + c8 * 16) = val;
        }
    }
    __syncthreads();

    // A fragments register-resident for all 8 k-steps
    const uint32_t aBase = smA + (uint32_t)((wr * 16 + (l & 15)) * (STRH * 2)) + ((l >> 4) & 1) * 16;
    uint32_t af[8][4];
#pragma unroll
    for (int ks = 0; ks < 8; ks++) ldsm_x4(af[ks], aBase + ks * 32);

    uint32_t kd[2][4];
#pragma unroll
    for (int h = 0; h < 2; h++)
#pragma unroll
        for (int s = 0; s < 4; s++) kd[h][s] = 0xFFFFFFFFu;

    const uint32_t bOff = (uint32_t)((wc * 64 + (l & 7) + ((l >> 4) & 1) * 8) * (STRH * 2)) + ((l >> 3) & 1) * 16;

    float rsq = 0.f;
    for (int u = 0; u < NTILES; u++) {
        if (u < NTILES - 1) {
            const int cb1 = (bx + (u + 1) * G) * NTILE;
            const uint32_t dstB = smB + (uint32_t)(((u + 1) & 1) * TBYTES);
#pragma unroll
            for (int v = 0; v < 8; v++) {
                int i = tid + v * 256;
                int col = i >> 4, k8 = i & 15;
                cp_async16(dstB + (uint32_t)(col * (STRH * 2) + k8 * 16),
                           g_xh + (cb1 + col) * D + k8 * 8);
            }
            cp_commit();
            if (tid < 128) rsq = g_sq[cb1 + tid];   // LDG hidden by MMA
            cp_wait1();
        } else {
            cp_wait0();
        }
        __syncthreads();

        float acc[8][4];
#pragma unroll
        for (int nf = 0; nf < 8; nf++)
#pragma unroll
            for (int q = 0; q < 4; q++) acc[nf][q] = 0.f;

        const uint32_t bBase = smB + (uint32_t)((u & 1) * TBYTES) + bOff;
#pragma unroll
        for (int ks = 0; ks < 8; ks++) {
            uint32_t b[4][4];
#pragma unroll
            for (int nf4 = 0; nf4 < 4; nf4++)
                ldsm_x4(b[nf4], bBase + nf4 * 16 * (STRH * 2) + ks * 32);
#pragma unroll
            for (int nf = 0; nf < 8; nf++)
                mma16816(acc[nf], af[ks], b[nf >> 1][(nf & 1) * 2], b[nf >> 1][(nf & 1) * 2 + 1]);
        }

        // branchless epilogue: key = bits(sq_j+512-2dot)&~0x1FF | id9, pair-min
        const float* sq1 = sqc + (u & 1) * 128;
        const uint32_t idu = (uint32_t)(u << 6);
#pragma unroll
        for (int nf = 0; nf < 8; nf++) {
            float2 sj = *(const float2*)&sq1[wc * 64 + nf * 8 + lane2 * 2];
            const uint32_t idb = idu | (uint32_t)((nf << 3) | (lane2 << 1));
#pragma unroll
            for (int h = 0; h < 2; h++) {
                float k0 = fmaf(-2.f, acc[nf][h * 2 + 0], sj.x);
                float k1 = fmaf(-2.f, acc[nf][h * 2 + 1], sj.y);
                uint32_t key0 = (__float_as_uint(k0) & 0xFFFFFE00u) | idb;
                uint32_t key1 = (__float_as_uint(k1) & 0xFFFFFE00u) | idb | 1u;
                ins4(min(key0, key1), kd[h]);
            }
        }

        if (u < NTILES - 1 && tid < 128) sqc[((u + 1) & 1) * 128 + tid] = rsq;
        __syncthreads();
    }

    // merge across the 4 lanes of each quad
    uint32_t t5[2][KEEP];
#pragma unroll
    for (int h = 0; h < 2; h++) {
#pragma unroll
        for (int s = 0; s < 4; s++) t5[h][s] = kd[h][s];
        t5[h][4] = 0xFFFFFFFFu;
#pragma unroll
        for (int s = 0; s < 4; s++)
            ins5(__shfl_xor_sync(0xffffffffu, kd[h][s], 1), t5[h]);
        uint32_t o[KEEP];
#pragma unroll
        for (int s = 0; s < KEEP; s++) o[s] = __shfl_xor_sync(0xffffffffu, t5[h][s], 2);
#pragma unroll
        for (int s = 0; s < KEEP; s++) ins5(o[s], t5[h]);
    }

    // cross-wc merge: wc==1 publishes keys, wc==0 decodes + merges + writes
    uint32_t* scr = (uint32_t*)(sm + SM_SCR);
    __syncthreads();
    if (wc == 1 && lane2 == 0) {
#pragma unroll
        for (int h = 0; h < 2; h++) {
            int rl = wr * 16 + (l >> 2) + h * 8;
#pragma unroll
            for (int s = 0; s < KEEP; s++) scr[rl * KEEP + s] = t5[h][s];
        }
    }
    __syncthreads();
    if (wc == 0 && lane2 == 0) {
#pragma unroll
        for (int h = 0; h < 2; h++) {
            int rl = wr * 16 + (l >> 2) + h * 8;
            uint32_t rk[KEEP]; int rj[KEEP];
#pragma unroll
            for (int s = 0; s < KEEP; s++) {
                uint32_t id = t5[h][s] & 0x1FFu;
                rk[s] = t5[h][s];
                rj[s] = bx * NTILE + (int)(id >> 6) * (G * NTILE) + (int)(id & 63);
            }
#pragma unroll
            for (int e = 0; e < KEEP; e++) {
                uint32_t ck = scr[rl * KEEP + e];
                uint32_t id = ck & 0x1FFu;
                int cj = bx * NTILE + (int)(id >> 6) * (G * NTILE) + 64 + (int)(id & 63);
#pragma unroll
                for (int s = 0; s < KEEP; s++) {
                    bool lt = ck < rk[s];
                    uint32_t nk = lt ? ck : rk[s];
                    int      nj = lt ? cj : rj[s];
                    ck = lt ? rk[s] : ck;
                    cj = lt ? rj[s] : cj;
                    rk[s] = nk; rj[s] = nj;
                }
            }
            int row = rowBase + rl;
#pragma unroll
            for (int s = 0; s < KEEP; s++)
                g_topI[(row * G + bx) * KEEP + s] = rj[s];
        }
    }
}

// ---------------------------------------------------------------------------
// Kernel C: exact fp32 rescoring of 40 candidates -> 5th NN -> hinge,
// fused deterministic mean via last-block reduction.
// ---------------------------------------------------------------------------
__global__ void finalize_kernel(const float* __restrict__ x, const float* __restrict__ p,
                                float* __restrict__ out) {
    __shared__ float shw[8];
    __shared__ float shr[256];
    __shared__ bool  amLast;
    int wid  = threadIdx.x >> 5;
    int row  = blockIdx.x * 8 + wid;
    int lane = threadIdx.x & 31;

    float4 xi = ((const float4*)(x + row * D))[lane];

    float t5d[5]; int t5i[5];
#pragma unroll
    for (int s = 0; s < 5; s++) { t5d[s] = __int_as_float(0x7f800000); t5i[s] = 0x7fffffff; }

    const int* cand = g_topI + row * G * KEEP;
    for (int c = 0; c < G * KEEP; c++) {
        int j = cand[c];
        float4 xj = ((const float4*)(x + j * D))[lane];
        float d0 = xi.x - xj.x, d1 = xi.y - xj.y, d2_ = xi.z - xj.z, d3 = xi.w - xj.w;
        float s = fmaf(d0, d0, fmaf(d1, d1, fmaf(d2_, d2_, d3 * d3)));
#pragma unroll
        for (int o = 16; o; o >>= 1) s += __shfl_xor_sync(0xffffffffu, s, o);
        float d2 = fmaxf(s, 1e-12f);
        if (better(d2, j, t5d[4], t5i[4])) {
            float cd = d2; int ci = j;
#pragma unroll
            for (int k = 0; k < 5; k++) {
                if (better(cd, ci, t5d[k], t5i[k])) {
                    float td = t5d[k]; t5d[k] = cd; cd = td;
                    int   ti = t5i[k]; t5i[k] = ci; ci = ti;
                }
            }
        }
    }
    int neg = t5i[4];

    float4 pi = ((const float4*)(p + row * D))[lane];
    float4 xn = ((const float4*)(x + neg * D))[lane];
    float ap0 = xi.x - pi.x + 1e-6f, ap1 = xi.y - pi.y + 1e-6f;
    float ap2 = xi.z - pi.z + 1e-6f, ap3 = xi.w - pi.w + 1e-6f;
    float an0 = xi.x - xn.x + 1e-6f, an1 = xi.y - xn.y + 1e-6f;
    float an2 = xi.z - xn.z + 1e-6f, an3 = xi.w - xn.w + 1e-6f;
    float sap = fmaf(ap0, ap0, fmaf(ap1, ap1, fmaf(ap2, ap2, ap3 * ap3)));
    float san = fmaf(an0, an0, fmaf(an1, an1, fmaf(an2, an2, an3 * an3)));
#pragma unroll
    for (int o = 16; o; o >>= 1) {
        sap += __shfl_xor_sync(0xffffffffu, sap, o);
        san += __shfl_xor_sync(0xffffffffu, san, o);
    }
    if (lane == 0)
        shw[wid] = fmaxf(sqrtf(sap) - sqrtf(san) + 0.3f, 0.f);
    __syncthreads();

    if (threadIdx.x == 0) {
        float s = 0.f;
#pragma unroll
        for (int i = 0; i < 8; i++) s += shw[i];
        g_partial[blockIdx.x] = s;
    }
    __threadfence();
    if (threadIdx.x == 0)
        amLast = (atomicInc(&g_cnt, 1023u) == 1023u);
    __syncthreads();

    if (amLast) {
        float s = 0.f;
        for (int i = threadIdx.x; i < 1024; i += 256) s += g_partial[i];
        shr[threadIdx.x] = s;
        __syncthreads();
        for (int o = 128; o; o >>= 1) {
            if (threadIdx.x < o) shr[threadIdx.x] += shr[threadIdx.x + o];
            __syncthreads();
        }
        if (threadIdx.x == 0) out[0] = shr[0] * (1.0f / N);
    }
}

// ---------------------------------------------------------------------------
extern "C" void kernel_launch(void* const* d_in, const int* in_sizes, int n_in,
                              void* d_out, int out_size) {
    const float* x   = (const float*)d_in[0];
    const float* pos = (const float*)d_in[1];
    float* out = (float*)d_out;

    cudaFuncSetAttribute(gram_top_kernel,
                         cudaFuncAttributeMaxDynamicSharedMemorySize, SM_TOTAL);

    prep_kernel<<<N / 8, 256>>>(x);
    gram_top_kernel<<<dim3(G, N / MT), 256, SM_TOTAL>>>();
    finalize_kernel<<<N / 8, 256>>>(x, pos, out);
}